// round 5
// baseline (speedup 1.0000x reference)
#include <cuda_runtime.h>
#include <cstddef>

#define BB 8
#define MM 8192
#define DD 256
#define HOPS 3

// Scratch state (allocation-free: __device__ globals)
__device__ float g_u[BB * DD];
__device__ float g_o[BB * DD];
__device__ float g_logits[BB * MM];
__device__ float g_w[BB * MM];

// ---------------------------------------------------------------------------
// K0: u = query, o = 0
// ---------------------------------------------------------------------------
__global__ void k_init(const float* __restrict__ q) {
    int i = blockIdx.x * 256 + threadIdx.x;   // 8 blocks x 256 = 2048 = BB*DD
    g_u[i] = q[i];
    g_o[i] = 0.0f;
}

// ---------------------------------------------------------------------------
// K1: logits[b,m] = gp[b,m] * dot(ms[b,m,:], u[b,:])
// warp-per-row, 64 rows per 256-thread CTA, u[b] held in registers per lane.
// Streams one 67 MB slice; should be DRAM-bound.
// ---------------------------------------------------------------------------
__global__ void k_logits(const float* __restrict__ ms,
                         const float* __restrict__ gp,
                         float* __restrict__ out_logits /* null unless last hop */) {
    const int ROWS_PER_BLOCK = 64;
    int row0 = blockIdx.x * ROWS_PER_BLOCK;
    int b = row0 / MM;                         // 64 | 8192 -> block never straddles b
    int lane = threadIdx.x & 31;
    int warp = threadIdx.x >> 5;

    __shared__ float su[DD];
    su[threadIdx.x] = g_u[b * DD + threadIdx.x];   // blockDim == DD == 256
    __syncthreads();

    // lane's slice of u: elements [lane*4, lane*4+4) and [128+lane*4, ...)
    float4 ub0 = reinterpret_cast<const float4*>(su)[lane];
    float4 ub1 = reinterpret_cast<const float4*>(su)[lane + 32];

    int r0 = row0 + warp * 8;                  // 8 rows per warp
#pragma unroll
    for (int i = 0; i < 8; i++) {
        int row = r0 + i;
        const float4* rp = reinterpret_cast<const float4*>(ms + (size_t)row * DD);
        float4 a0 = rp[lane];
        float4 a1 = rp[lane + 32];
        float s = a0.x * ub0.x + a0.y * ub0.y + a0.z * ub0.z + a0.w * ub0.w
                + a1.x * ub1.x + a1.y * ub1.y + a1.z * ub1.z + a1.w * ub1.w;
#pragma unroll
        for (int off = 16; off; off >>= 1)
            s += __shfl_xor_sync(0xffffffffu, s, off);
        if (lane == 0) {
            float v = s * gp[row];
            g_logits[row] = v;
            if (out_logits) out_logits[row] = v;
        }
    }
}

// ---------------------------------------------------------------------------
// K2: softmax over M per batch. One CTA per b (8 CTAs, 256 threads).
// Non-last hops: w = prob * gp (pre-scaled weight for the o_k pass).
// Last hop: write prob_soft to d_out.
// ---------------------------------------------------------------------------
__global__ void k_softmax(const float* __restrict__ gp,
                          float* __restrict__ out_prob /* null unless last hop */) {
    int b = blockIdx.x;
    int tid = threadIdx.x;
    const float* l = g_logits + b * MM;
    __shared__ float red[256];

    float lmax = -1e30f;
    for (int i = tid; i < MM; i += 256) lmax = fmaxf(lmax, l[i]);
    red[tid] = lmax;
    __syncthreads();
    for (int s = 128; s > 0; s >>= 1) {
        if (tid < s) red[tid] = fmaxf(red[tid], red[tid + s]);
        __syncthreads();
    }
    float bmax = red[0];
    __syncthreads();

    float lsum = 0.0f;
    for (int i = tid; i < MM; i += 256) lsum += __expf(l[i] - bmax);
    red[tid] = lsum;
    __syncthreads();
    for (int s = 128; s > 0; s >>= 1) {
        if (tid < s) red[tid] += red[tid + s];
        __syncthreads();
    }
    float inv = 1.0f / red[0];

    for (int i = tid; i < MM; i += 256) {
        float p = __expf(l[i] - bmax) * inv;
        if (out_prob) out_prob[b * MM + i] = p;
        else          g_w[b * MM + i] = p * gp[b * MM + i];
    }
}

// ---------------------------------------------------------------------------
// K3: o[b,d] += sum_m w[b,m] * ms[b,m,d]  over a 128-row chunk per CTA.
// thread d (256 threads) accumulates in a register; one atomicAdd per thread.
// Streams one 67 MB slice; should be DRAM-bound.
// ---------------------------------------------------------------------------
__global__ void k_ok(const float* __restrict__ ms) {
    const int CHUNK = 128;
    int row0 = blockIdx.x * CHUNK;
    int b = row0 / MM;                         // 128 | 8192
    int d = threadIdx.x;

    __shared__ float sw[CHUNK];
    if (threadIdx.x < CHUNK) sw[threadIdx.x] = g_w[row0 + threadIdx.x];
    __syncthreads();

    const float* base = ms + (size_t)row0 * DD + d;
    float acc = 0.0f;
#pragma unroll 8
    for (int m = 0; m < CHUNK; m++)
        acc = fmaf(sw[m], base[(size_t)m * DD], acc);

    atomicAdd(&g_o[b * DD + d], acc);
}

// ---------------------------------------------------------------------------
// K4: u += o; o = 0
// ---------------------------------------------------------------------------
__global__ void k_update() {
    int i = blockIdx.x * 256 + threadIdx.x;    // 8 blocks
    g_u[i] += g_o[i];
    g_o[i] = 0.0f;
}

// ---------------------------------------------------------------------------
extern "C" void kernel_launch(void* const* d_in, const int* in_sizes, int n_in,
                              void* d_out, int out_size) {
    const float* q  = (const float*)d_in[0];   // query_vector (8,256)
    const float* gp = (const float*)d_in[1];   // global_pointer (8,8192)
    const float* ms = (const float*)d_in[2];   // m_story (4,8,8192,256)

    float* out        = (float*)d_out;
    float* out_prob   = out;                   // prob_soft  : first  B*M
    float* out_logits = out + BB * MM;         // prob_logits: second B*M

    k_init<<<8, 256>>>(q);

    for (int h = 0; h < HOPS; h++) {
        bool last = (h == HOPS - 1);
        const float* msA = ms + (size_t)h * BB * MM * DD;

        k_logits<<<BB * MM / 64, 256>>>(msA, gp, last ? out_logits : nullptr);
        k_softmax<<<BB, 256>>>(gp, last ? out_prob : nullptr);

        if (!last) {
            // Last hop's o_k / u-update is dead (outputs are prob/logits only):
            // skipping it saves one full 67 MB slice read.
            const float* msC = ms + (size_t)(h + 1) * BB * MM * DD;
            k_ok<<<BB * MM / 128, 256>>>(msC);
            k_update<<<8, 256>>>();
        }
    }
}

// round 8
// speedup vs baseline: 1.3417x; 1.3417x over previous
#include <cuda_runtime.h>
#include <cstddef>

#define BB 8
#define MM 8192
#define DD 256
#define HOPS 3

// Scratch (allocation-free __device__ globals)
__device__ float g_o[BB * DD];        // cumulative sum of o_k across hops (u = q + g_o)
__device__ float g_logits[BB * MM];
__device__ float g_pmax[BB * 128];    // per-block softmax partial max   (128 blocks per b)
__device__ float g_psum[BB * 128];    // per-block partial sum of exp(l - pmax)
__device__ float g_bmax[BB];
__device__ float g_binv[BB];          // 1 / sum_exp

// ---------------------------------------------------------------------------
// K0: zero the cumulative o accumulator
// ---------------------------------------------------------------------------
__global__ void k_init() {
    g_o[blockIdx.x * 256 + threadIdx.x] = 0.0f;   // 8 blocks x 256
}

// ---------------------------------------------------------------------------
// K1: logits[b,m] = gp[b,m] * dot(ms[b,m,:], q[b,:] + g_o[b,:])
//     + per-block softmax stats (max, sum-exp) into g_pmax/g_psum.
// warp-per-row, 64 rows / 256-thread CTA, float4 loads. DRAM-streaming.
// ---------------------------------------------------------------------------
__global__ void __launch_bounds__(256)
k_logits(const float* __restrict__ ms,
         const float* __restrict__ q,
         const float* __restrict__ gp,
         float* __restrict__ out_logits /* null unless last hop */) {
    const int ROWS = 64;
    int row0 = blockIdx.x * ROWS;
    int b = row0 >> 13;                    // / 8192 ; 64 | 8192 -> no straddle
    int lane = threadIdx.x & 31;
    int warp = threadIdx.x >> 5;

    __shared__ float su[DD];
    __shared__ float srow[ROWS];
    su[threadIdx.x] = q[b * DD + threadIdx.x] + g_o[b * DD + threadIdx.x];
    __syncthreads();

    float4 ub0 = reinterpret_cast<const float4*>(su)[lane];
    float4 ub1 = reinterpret_cast<const float4*>(su)[lane + 32];

    int r0 = row0 + warp * 8;
#pragma unroll
    for (int i = 0; i < 8; i++) {
        int row = r0 + i;
        const float4* rp = reinterpret_cast<const float4*>(ms + (size_t)row * DD);
        float4 a0 = rp[lane];
        float4 a1 = rp[lane + 32];
        float s = a0.x * ub0.x + a0.y * ub0.y + a0.z * ub0.z + a0.w * ub0.w
                + a1.x * ub1.x + a1.y * ub1.y + a1.z * ub1.z + a1.w * ub1.w;
#pragma unroll
        for (int off = 16; off; off >>= 1)
            s += __shfl_xor_sync(0xffffffffu, s, off);
        if (lane == 0) {
            float v = s * gp[row];
            g_logits[row] = v;
            srow[warp * 8 + i] = v;
            if (out_logits) out_logits[row] = v;
        }
    }
    __syncthreads();

    // Block-local softmax stats over the 64 logits (warp 0 only)
    if (warp == 0) {
        float v0 = srow[lane];
        float v1 = srow[lane + 32];
        float m = fmaxf(v0, v1);
#pragma unroll
        for (int off = 16; off; off >>= 1)
            m = fmaxf(m, __shfl_xor_sync(0xffffffffu, m, off));
        float s = __expf(v0 - m) + __expf(v1 - m);
#pragma unroll
        for (int off = 16; off; off >>= 1)
            s += __shfl_xor_sync(0xffffffffu, s, off);
        if (lane == 0) {
            g_pmax[blockIdx.x] = m;    // blocks within b are contiguous
            g_psum[blockIdx.x] = s;
        }
    }
}

// ---------------------------------------------------------------------------
// K2: merge 128 partial (max,sum) pairs per b -> (bmax, 1/sum). 1 CTA, 8 warps.
// ---------------------------------------------------------------------------
__global__ void k_combine() {
    int b = threadIdx.x >> 5;
    int lane = threadIdx.x & 31;
    float m = -1e30f, s = 0.0f;
#pragma unroll
    for (int i = 0; i < 4; i++) {
        int idx = b * 128 + i * 32 + lane;
        float pm = g_pmax[idx], ps = g_psum[idx];
        float nm = fmaxf(m, pm);
        s = s * __expf(m - nm) + ps * __expf(pm - nm);
        m = nm;
    }
#pragma unroll
    for (int off = 16; off; off >>= 1) {
        float om = __shfl_xor_sync(0xffffffffu, m, off);
        float os = __shfl_xor_sync(0xffffffffu, s, off);
        float nm = fmaxf(m, om);
        s = s * __expf(m - nm) + os * __expf(om - nm);
        m = nm;
    }
    if (lane == 0) {
        g_bmax[b] = m;
        g_binv[b] = 1.0f / s;
    }
}

// ---------------------------------------------------------------------------
// K3: o[b,:] += sum_m softmax(l)[m] * gp[m] * ms[b,m,:]
// 64-row chunk per CTA (grid 1024), float4 loads, w computed inline from
// logits + softmax stats. smem cross-row-group reduce, then 4 atomics/thread64.
// ---------------------------------------------------------------------------
__global__ void __launch_bounds__(256)
k_ok(const float* __restrict__ ms, const float* __restrict__ gp) {
    const int CHUNK = 64;
    int row0 = blockIdx.x * CHUNK;
    int b = row0 >> 13;
    int c = threadIdx.x & 63;              // float4 column 0..63
    int g = threadIdx.x >> 6;              // row group 0..3

    __shared__ float sw[CHUNK];
    __shared__ float4 sred[4][64];
    if (threadIdx.x < CHUNK) {
        int r = row0 + threadIdx.x;
        sw[threadIdx.x] = __expf(g_logits[r] - g_bmax[b]) * g_binv[b] * gp[r];
    }
    __syncthreads();

    float4 acc = make_float4(0.f, 0.f, 0.f, 0.f);
#pragma unroll
    for (int i = 0; i < 16; i++) {
        int m = g + i * 4;
        float4 a = reinterpret_cast<const float4*>(ms + (size_t)(row0 + m) * DD)[c];
        float w = sw[m];
        acc.x = fmaf(w, a.x, acc.x);
        acc.y = fmaf(w, a.y, acc.y);
        acc.z = fmaf(w, a.z, acc.z);
        acc.w = fmaf(w, a.w, acc.w);
    }
    sred[g][c] = acc;
    __syncthreads();

    if (g == 0) {
        float4 r0 = sred[0][c], r1 = sred[1][c], r2 = sred[2][c], r3 = sred[3][c];
        float* o = g_o + b * DD + c * 4;
        atomicAdd(o + 0, r0.x + r1.x + r2.x + r3.x);
        atomicAdd(o + 1, r0.y + r1.y + r2.y + r3.y);
        atomicAdd(o + 2, r0.z + r1.z + r2.z + r3.z);
        atomicAdd(o + 3, r0.w + r1.w + r2.w + r3.w);
    }
}

// ---------------------------------------------------------------------------
// K4 (last hop only): prob_soft = softmax(logits), massively parallel
// ---------------------------------------------------------------------------
__global__ void k_prob(float* __restrict__ out_prob) {
    int i = blockIdx.x * 256 + threadIdx.x;    // 256 blocks x 256 = 65536
    int b = i >> 13;
    out_prob[i] = __expf(g_logits[i] - g_bmax[b]) * g_binv[b];
}

// ---------------------------------------------------------------------------
extern "C" void kernel_launch(void* const* d_in, const int* in_sizes, int n_in,
                              void* d_out, int out_size) {
    const float* q  = (const float*)d_in[0];   // (8,256)
    const float* gp = (const float*)d_in[1];   // (8,8192)
    const float* ms = (const float*)d_in[2];   // (4,8,8192,256)

    float* out        = (float*)d_out;
    float* out_prob   = out;                   // prob_soft  : first  B*M
    float* out_logits = out + BB * MM;         // prob_logits: second B*M

    const size_t SLICE = (size_t)BB * MM * DD;

    k_init<<<8, 256>>>();

    for (int h = 0; h < HOPS; h++) {
        bool last = (h == HOPS - 1);
        k_logits<<<BB * MM / 64, 256>>>(ms + (size_t)h * SLICE, q, gp,
                                        last ? out_logits : nullptr);
        k_combine<<<1, 256>>>();
        if (!last) {
            // Slice h+1 is read here and again by the next k_logits while it
            // is still L2-resident (67 MB < 126 MB L2) — keep this ordering.
            k_ok<<<BB * MM / 64, 256>>>(ms + (size_t)(h + 1) * SLICE, gp);
        } else {
            k_prob<<<BB * MM / 256, 256>>>(out_prob);
        }
    }
}